// round 3
// baseline (speedup 1.0000x reference)
#include <cuda_runtime.h>
#include <math.h>

#define DIMD 1024
#define NH   16
#define HD   64

// ---------------- scratch (device globals: no allocation allowed) ----------
// 16384 * 1024 floats = 64 MB each
__device__ float g_Q[16384 * 1024];
__device__ float g_K[16384 * 1024];
__device__ float g_V[16384 * 1024];
__device__ float g_A[16384 * 1024];
__device__ float g_KV[64 * 64 * 64];   // [B*H][d][e]
__device__ float g_Z [64 * 64];        // [B*H][d]

// ---------------- zero kernel ----------------------------------------------
__global__ void zero_kernel(float* __restrict__ p, int n) {
    int i = blockIdx.x * blockDim.x + threadIdx.x;
    if (i < n) p[i] = 0.0f;
}

// ---------------- GEMM: C[m,n] = sum_k A[m,k]*B[n,k] + bias[n] -------------
// A: [M,K] row-major, B: [N=1024,K] row-major (torch Linear weight), C: [M,1024]
// ACT=1 applies phi(x) = elu(x)+1 = (x>0 ? x+1 : exp(x))
constexpr int BM = 128, BN = 128, BK = 16;

template <int ACT>
__global__ __launch_bounds__(256, 2)
void gemm_abT(const float* __restrict__ A, const float* __restrict__ B,
              const float* __restrict__ bias, float* __restrict__ C,
              int M, int K)
{
    __shared__ float As[BK][BM + 4];
    __shared__ float Bs[BK][BN + 4];

    const int tid = threadIdx.x;
    const int bm  = blockIdx.y * BM;
    const int bn  = blockIdx.x * BN;
    const int tx  = tid & 15;   // 0..15 -> n tile
    const int ty  = tid >> 4;   // 0..15 -> m tile

    float acc[8][8];
#pragma unroll
    for (int i = 0; i < 8; i++)
#pragma unroll
        for (int j = 0; j < 8; j++) acc[i][j] = 0.0f;

    for (int k0 = 0; k0 < K; k0 += BK) {
        // 512 float4 per operand tile; 256 threads -> 2 each
#pragma unroll
        for (int li = 0; li < 2; li++) {
            int id  = tid + li * 256;         // 0..511
            int row = id >> 2;                // 0..127
            int k4  = (id & 3) * 4;           // 0,4,8,12
            float4 a = *(const float4*)&A[(size_t)(bm + row) * K + k0 + k4];
            As[k4 + 0][row] = a.x; As[k4 + 1][row] = a.y;
            As[k4 + 2][row] = a.z; As[k4 + 3][row] = a.w;
            float4 b = *(const float4*)&B[(size_t)(bn + row) * K + k0 + k4];
            Bs[k4 + 0][row] = b.x; Bs[k4 + 1][row] = b.y;
            Bs[k4 + 2][row] = b.z; Bs[k4 + 3][row] = b.w;
        }
        __syncthreads();

#pragma unroll
        for (int k = 0; k < BK; k++) {
            float4 a0 = *(const float4*)&As[k][ty * 8];
            float4 a1 = *(const float4*)&As[k][ty * 8 + 4];
            float4 b0 = *(const float4*)&Bs[k][tx * 8];
            float4 b1 = *(const float4*)&Bs[k][tx * 8 + 4];
            float av[8] = {a0.x, a0.y, a0.z, a0.w, a1.x, a1.y, a1.z, a1.w};
            float bv[8] = {b0.x, b0.y, b0.z, b0.w, b1.x, b1.y, b1.z, b1.w};
#pragma unroll
            for (int i = 0; i < 8; i++)
#pragma unroll
                for (int j = 0; j < 8; j++)
                    acc[i][j] += av[i] * bv[j];
        }
        __syncthreads();
    }

    // epilogue
    float bb[8];
#pragma unroll
    for (int j = 0; j < 8; j++) bb[j] = bias[bn + tx * 8 + j];

#pragma unroll
    for (int i = 0; i < 8; i++) {
        int m = bm + ty * 8 + i;
        float v[8];
#pragma unroll
        for (int j = 0; j < 8; j++) {
            float t = acc[i][j] + bb[j];
            if (ACT) t = (t > 0.0f) ? (t + 1.0f) : expf(t);
            v[j] = t;
        }
        float* cp = &C[(size_t)m * DIMD + bn + tx * 8];
        *(float4*)(cp)     = make_float4(v[0], v[1], v[2], v[3]);
        *(float4*)(cp + 4) = make_float4(v[4], v[5], v[6], v[7]);
    }
}

// ---------------- KV state: KV[bh][d][e] = sum_n K[n,d]*V[n,e]; Z = sum K --
#define KV_SPLIT 8

__global__ __launch_bounds__(256)
void kv_kernel(const float* __restrict__ Kmat, const float* __restrict__ Vmat,
               float* __restrict__ KV, float* __restrict__ Z, int seq)
{
    const int bh    = blockIdx.x / KV_SPLIT;
    const int chunk = blockIdx.x % KV_SPLIT;
    const int b = bh / NH, h = bh % NH;
    const int rowsPer = seq / KV_SPLIT;
    const int n0 = chunk * rowsPer;

    const int tid = threadIdx.x;
    const int ti = tid >> 4;   // d group
    const int tj = tid & 15;   // e group

    __shared__ float Ks[8][64];
    __shared__ float Vs[8][64];

    float acc[4][4];
#pragma unroll
    for (int i = 0; i < 4; i++)
#pragma unroll
        for (int j = 0; j < 4; j++) acc[i][j] = 0.0f;
    float z = 0.0f;

    const size_t base = ((size_t)b * seq) * DIMD + h * HD;

    for (int n = n0; n < n0 + rowsPer; n += 8) {
#pragma unroll
        for (int li = 0; li < 2; li++) {
            int idx = tid + li * 256;      // 0..511
            int r = idx >> 6, c = idx & 63;
            size_t g = base + (size_t)(n + r) * DIMD + c;
            Ks[r][c] = Kmat[g];
            Vs[r][c] = Vmat[g];
        }
        __syncthreads();
#pragma unroll
        for (int r = 0; r < 8; r++) {
            float kd[4], ve[4];
#pragma unroll
            for (int i = 0; i < 4; i++) kd[i] = Ks[r][ti * 4 + i];
#pragma unroll
            for (int j = 0; j < 4; j++) ve[j] = Vs[r][tj * 4 + j];
#pragma unroll
            for (int i = 0; i < 4; i++)
#pragma unroll
                for (int j = 0; j < 4; j++)
                    acc[i][j] += kd[i] * ve[j];
            if (tid < 64) z += Ks[r][tid];
        }
        __syncthreads();
    }

    float* kvp = KV + (size_t)bh * HD * HD;
#pragma unroll
    for (int i = 0; i < 4; i++)
#pragma unroll
        for (int j = 0; j < 4; j++)
            atomicAdd(&kvp[(ti * 4 + i) * HD + tj * 4 + j], acc[i][j]);
    if (tid < 64) atomicAdd(&Z[bh * HD + tid], z);
}

// ---------------- apply: out[n,e] = (Q[n,:]·KV[:,e]) / (Q[n,:]·Z + eps) ----
__global__ __launch_bounds__(256)
void attn_kernel(const float* __restrict__ Qmat, const float* __restrict__ KV,
                 const float* __restrict__ Z, float* __restrict__ Out, int seq)
{
    const int bh = blockIdx.x;
    const int b = bh / NH, h = bh % NH;
    const int n0 = blockIdx.y * 64;
    const int tid = threadIdx.x;

    __shared__ float KVs[64][64];
    __shared__ float Qs[64][64];
    __shared__ float Zs[64];

    const float* kvp = KV + (size_t)bh * HD * HD;
    for (int i = tid; i < 4096; i += 256) KVs[i >> 6][i & 63] = kvp[i];
    if (tid < 64) Zs[tid] = Z[bh * HD + tid];

    const size_t base = ((size_t)b * seq) * DIMD + h * HD;
    for (int i = tid; i < 4096; i += 256) {
        int r = i >> 6, c = i & 63;
        Qs[r][c] = Qmat[base + (size_t)(n0 + r) * DIMD + c];
    }
    __syncthreads();

    const int r = tid >> 2;   // row within tile 0..63
    const int g = tid & 3;    // 16-wide column group

    float out[16];
#pragma unroll
    for (int e = 0; e < 16; e++) out[e] = 0.0f;
    float nrm = 0.0f;

#pragma unroll
    for (int d = 0; d < 64; d++) {
        float q = Qs[r][d];
        nrm += q * Zs[d];
#pragma unroll
        for (int e = 0; e < 16; e++)
            out[e] += q * KVs[d][g * 16 + e];
    }

    float inv = 1.0f / (nrm + 1e-6f);
    float* op = Out + base + (size_t)(n0 + r) * DIMD + g * 16;
#pragma unroll
    for (int e = 0; e < 16; e += 4)
        *(float4*)(op + e) = make_float4(out[e] * inv, out[e + 1] * inv,
                                         out[e + 2] * inv, out[e + 3] * inv);
}

// ---------------- launcher --------------------------------------------------
extern "C" void kernel_launch(void* const* d_in, const int* in_sizes, int n_in,
                              void* d_out, int out_size)
{
    const float* x  = (const float*)d_in[0];
    const float* Wq = (const float*)d_in[1];
    const float* bq = (const float*)d_in[2];
    const float* Wk = (const float*)d_in[3];
    const float* bk = (const float*)d_in[4];
    const float* Wv = (const float*)d_in[5];
    const float* bv = (const float*)d_in[6];
    const float* Wo = (const float*)d_in[7];
    const float* bo = (const float*)d_in[8];

    const int M   = in_sizes[0] / DIMD;   // B*N = 16384
    const int B   = 4;
    const int seq = M / B;                // 4096

    float *Qp, *Kp, *Vp, *Ap, *KVp, *Zp;
    cudaGetSymbolAddress((void**)&Qp,  g_Q);
    cudaGetSymbolAddress((void**)&Kp,  g_K);
    cudaGetSymbolAddress((void**)&Vp,  g_V);
    cudaGetSymbolAddress((void**)&Ap,  g_A);
    cudaGetSymbolAddress((void**)&KVp, g_KV);
    cudaGetSymbolAddress((void**)&Zp,  g_Z);

    dim3 gblk(DIMD / BN, M / BM);   // (8, 128)

    // projections (phi fused into Q,K)
    gemm_abT<1><<<gblk, 256>>>(x, Wq, bq, Qp, M, DIMD);
    gemm_abT<1><<<gblk, 256>>>(x, Wk, bk, Kp, M, DIMD);
    gemm_abT<0><<<gblk, 256>>>(x, Wv, bv, Vp, M, DIMD);

    // zero KV / Z accumulators
    zero_kernel<<<(64 * 64 * 64 + 255) / 256, 256>>>(KVp, 64 * 64 * 64);
    zero_kernel<<<(64 * 64 + 255) / 256, 256>>>(Zp, 64 * 64);

    // KV state + Z (split-K over sequence, atomic combine)
    kv_kernel<<<B * NH * KV_SPLIT, 256>>>(Kp, Vp, KVp, Zp, seq);

    // attention apply + normalization
    attn_kernel<<<dim3(B * NH, seq / 64), 256>>>(Qp, KVp, Zp, Ap, seq);

    // output projection -> d_out
    gemm_abT<0><<<gblk, 256>>>(Ap, Wo, bo, (float*)d_out, M, DIMD);
}

// round 4
// speedup vs baseline: 2.6404x; 2.6404x over previous
#include <cuda_runtime.h>
#include <math.h>
#include <stdint.h>

#define DIMD 1024
#define NH   16
#define HD   64

// ---------------- scratch (device globals: no allocation allowed) ----------
__device__ float g_Q[16384 * 1024];
__device__ float g_K[16384 * 1024];
__device__ float g_V[16384 * 1024];
__device__ float g_A[16384 * 1024];
__device__ float g_KV[64 * 64 * 64];   // [B*H][d][e]
__device__ float g_Z [64 * 64];        // [B*H][d]

// ---------------- zero kernel (KV + Z in one launch) ------------------------
__global__ void zero_kv_kernel(float* __restrict__ kv, float* __restrict__ z) {
    int i = blockIdx.x * blockDim.x + threadIdx.x;
    if (i < 64 * 64 * 64) kv[i] = 0.0f;
    if (i < 64 * 64)      z[i]  = 0.0f;
}

// ---------------- tf32 helpers ----------------------------------------------
__device__ __forceinline__ uint32_t f2tf32(float f) {
    uint32_t u;
    asm("cvt.rna.tf32.f32 %0, %1;" : "=r"(u) : "f"(f));
    return u;
}

__device__ __forceinline__ void mma_tf32(float* d, const uint32_t* a, const uint32_t* b) {
    asm volatile(
        "mma.sync.aligned.m16n8k8.row.col.f32.tf32.tf32.f32 "
        "{%0,%1,%2,%3}, {%4,%5,%6,%7}, {%8,%9}, {%0,%1,%2,%3};"
        : "+f"(d[0]), "+f"(d[1]), "+f"(d[2]), "+f"(d[3])
        : "r"(a[0]), "r"(a[1]), "r"(a[2]), "r"(a[3]),
          "r"(b[0]), "r"(b[1]));
}

// ---------------- tf32 GEMM: C[m,n] = sum_k A[m,k]*B[n,k] + bias[n] ---------
// A: [M,K] row-major; B: [1024,K] row-major (torch Linear weight); C: [M,1024]
// ACT=1 applies phi(x) = elu(x)+1 = (x>0 ? x+1 : exp(x))
constexpr int BM = 128, BN = 128, BK = 32;
constexpr int SKW = BK + 4;   // smem row stride (36): conflict-free frag loads

template <int ACT>
__global__ __launch_bounds__(256)
void gemm_tf32(const float* __restrict__ A, const float* __restrict__ B,
               const float* __restrict__ bias, float* __restrict__ C,
               int M, int K)
{
    __shared__ uint32_t As[BM][SKW];
    __shared__ uint32_t Bs[BN][SKW];

    const int tid  = threadIdx.x;
    const int lane = tid & 31;
    const int warp = tid >> 5;
    const int wm   = warp & 1;    // 0..1 : 64-row slab
    const int wn   = warp >> 1;   // 0..3 : 32-col slab
    const int bm   = blockIdx.y * BM;
    const int bn   = blockIdx.x * BN;

    const int g  = lane >> 2;     // 0..7
    const int t4 = lane & 3;      // 0..3

    float acc[4][4][4];
#pragma unroll
    for (int mt = 0; mt < 4; mt++)
#pragma unroll
        for (int nt = 0; nt < 4; nt++)
#pragma unroll
            for (int r = 0; r < 4; r++) acc[mt][nt][r] = 0.0f;

    // global tile staging: 128 rows x 32 k = 1024 float4 per operand,
    // 256 threads -> 4 float4 each.  id: row = id>>3, k4 = (id&7)*4
    float4 pa[4], pb[4];

#pragma unroll
    for (int l = 0; l < 4; l++) {
        int id = tid + 256 * l;
        int row = id >> 3, c4 = (id & 7) * 4;
        pa[l] = *(const float4*)&A[(size_t)(bm + row) * K + c4];
        pb[l] = *(const float4*)&B[(size_t)(bn + row) * K + c4];
    }

    for (int k0 = 0; k0 < K; k0 += BK) {
        // commit prefetched tile to smem (tf32-rounded)
#pragma unroll
        for (int l = 0; l < 4; l++) {
            int id = tid + 256 * l;
            int row = id >> 3, c4 = (id & 7) * 4;
            As[row][c4 + 0] = f2tf32(pa[l].x);
            As[row][c4 + 1] = f2tf32(pa[l].y);
            As[row][c4 + 2] = f2tf32(pa[l].z);
            As[row][c4 + 3] = f2tf32(pa[l].w);
            Bs[row][c4 + 0] = f2tf32(pb[l].x);
            Bs[row][c4 + 1] = f2tf32(pb[l].y);
            Bs[row][c4 + 2] = f2tf32(pb[l].z);
            Bs[row][c4 + 3] = f2tf32(pb[l].w);
        }
        __syncthreads();

        // prefetch next tile (LDG latency hidden under mma block)
        if (k0 + BK < K) {
#pragma unroll
            for (int l = 0; l < 4; l++) {
                int id = tid + 256 * l;
                int row = id >> 3, c4 = (id & 7) * 4;
                pa[l] = *(const float4*)&A[(size_t)(bm + row) * K + k0 + BK + c4];
                pb[l] = *(const float4*)&B[(size_t)(bn + row) * K + k0 + BK + c4];
            }
        }

#pragma unroll
        for (int kk = 0; kk < BK; kk += 8) {
            uint32_t af[4][4], bf[4][2];
#pragma unroll
            for (int mt = 0; mt < 4; mt++) {
                int r = wm * 64 + mt * 16 + g;
                af[mt][0] = As[r][kk + t4];
                af[mt][1] = As[r + 8][kk + t4];
                af[mt][2] = As[r][kk + 4 + t4];
                af[mt][3] = As[r + 8][kk + 4 + t4];
            }
#pragma unroll
            for (int nt = 0; nt < 4; nt++) {
                int c = wn * 32 + nt * 8 + g;
                bf[nt][0] = Bs[c][kk + t4];
                bf[nt][1] = Bs[c][kk + 4 + t4];
            }
#pragma unroll
            for (int mt = 0; mt < 4; mt++)
#pragma unroll
                for (int nt = 0; nt < 4; nt++)
                    mma_tf32(acc[mt][nt], af[mt], bf[nt]);
        }
        __syncthreads();
    }

    // epilogue: d0/d1 -> (row, col..col+1), d2/d3 -> (row+8, col..col+1)
#pragma unroll
    for (int mt = 0; mt < 4; mt++) {
#pragma unroll
        for (int nt = 0; nt < 4; nt++) {
            int row = bm + wm * 64 + mt * 16 + g;
            int col = bn + wn * 32 + nt * 8 + t4 * 2;
            float b0 = bias[col], b1 = bias[col + 1];

            float v0 = acc[mt][nt][0] + b0;
            float v1 = acc[mt][nt][1] + b1;
            float v2 = acc[mt][nt][2] + b0;
            float v3 = acc[mt][nt][3] + b1;
            if (ACT) {
                v0 = (v0 > 0.0f) ? (v0 + 1.0f) : expf(v0);
                v1 = (v1 > 0.0f) ? (v1 + 1.0f) : expf(v1);
                v2 = (v2 > 0.0f) ? (v2 + 1.0f) : expf(v2);
                v3 = (v3 > 0.0f) ? (v3 + 1.0f) : expf(v3);
            }
            *(float2*)&C[(size_t)row * DIMD + col]       = make_float2(v0, v1);
            *(float2*)&C[(size_t)(row + 8) * DIMD + col] = make_float2(v2, v3);
        }
    }
}

// ---------------- KV state: KV[bh][d][e] = sum_n K[n,d]*V[n,e]; Z = sum K --
#define KV_SPLIT 8

__global__ __launch_bounds__(256)
void kv_kernel(const float* __restrict__ Kmat, const float* __restrict__ Vmat,
               float* __restrict__ KV, float* __restrict__ Z, int seq)
{
    const int bh    = blockIdx.x / KV_SPLIT;
    const int chunk = blockIdx.x % KV_SPLIT;
    const int b = bh / NH, h = bh % NH;
    const int rowsPer = seq / KV_SPLIT;
    const int n0 = chunk * rowsPer;

    const int tid = threadIdx.x;
    const int ti = tid >> 4;
    const int tj = tid & 15;

    __shared__ float Ks[8][64];
    __shared__ float Vs[8][64];

    float acc[4][4];
#pragma unroll
    for (int i = 0; i < 4; i++)
#pragma unroll
        for (int j = 0; j < 4; j++) acc[i][j] = 0.0f;
    float z = 0.0f;

    const size_t base = ((size_t)b * seq) * DIMD + h * HD;

    for (int n = n0; n < n0 + rowsPer; n += 8) {
#pragma unroll
        for (int li = 0; li < 2; li++) {
            int idx = tid + li * 256;
            int r = idx >> 6, c = idx & 63;
            size_t gaddr = base + (size_t)(n + r) * DIMD + c;
            Ks[r][c] = Kmat[gaddr];
            Vs[r][c] = Vmat[gaddr];
        }
        __syncthreads();
#pragma unroll
        for (int r = 0; r < 8; r++) {
            float kd[4], ve[4];
#pragma unroll
            for (int i = 0; i < 4; i++) kd[i] = Ks[r][ti * 4 + i];
#pragma unroll
            for (int j = 0; j < 4; j++) ve[j] = Vs[r][tj * 4 + j];
#pragma unroll
            for (int i = 0; i < 4; i++)
#pragma unroll
                for (int j = 0; j < 4; j++)
                    acc[i][j] += kd[i] * ve[j];
            if (tid < 64) z += Ks[r][tid];
        }
        __syncthreads();
    }

    float* kvp = KV + (size_t)bh * HD * HD;
#pragma unroll
    for (int i = 0; i < 4; i++)
#pragma unroll
        for (int j = 0; j < 4; j++)
            atomicAdd(&kvp[(ti * 4 + i) * HD + tj * 4 + j], acc[i][j]);
    if (tid < 64) atomicAdd(&Z[bh * HD + tid], z);
}

// ---------------- apply: out[n,e] = (Q[n,:]·KV[:,e]) / (Q[n,:]·Z + eps) ----
__global__ __launch_bounds__(256)
void attn_kernel(const float* __restrict__ Qmat, const float* __restrict__ KV,
                 const float* __restrict__ Z, float* __restrict__ Out, int seq)
{
    const int bh = blockIdx.x;
    const int b = bh / NH, h = bh % NH;
    const int n0 = blockIdx.y * 64;
    const int tid = threadIdx.x;

    __shared__ float KVs[64][64];
    __shared__ float Qs[64][64];
    __shared__ float Zs[64];

    const float* kvp = KV + (size_t)bh * HD * HD;
    for (int i = tid; i < 4096; i += 256) KVs[i >> 6][i & 63] = kvp[i];
    if (tid < 64) Zs[tid] = Z[bh * HD + tid];

    const size_t base = ((size_t)b * seq) * DIMD + h * HD;
    for (int i = tid; i < 4096; i += 256) {
        int r = i >> 6, c = i & 63;
        Qs[r][c] = Qmat[base + (size_t)(n0 + r) * DIMD + c];
    }
    __syncthreads();

    const int r = tid >> 2;
    const int g = tid & 3;

    float out[16];
#pragma unroll
    for (int e = 0; e < 16; e++) out[e] = 0.0f;
    float nrm = 0.0f;

#pragma unroll
    for (int d = 0; d < 64; d++) {
        float q = Qs[r][d];
        nrm += q * Zs[d];
#pragma unroll
        for (int e = 0; e < 16; e++)
            out[e] += q * KVs[d][g * 16 + e];
    }

    float inv = 1.0f / (nrm + 1e-6f);
    float* op = Out + base + (size_t)(n0 + r) * DIMD + g * 16;
#pragma unroll
    for (int e = 0; e < 16; e += 4)
        *(float4*)(op + e) = make_float4(out[e] * inv, out[e + 1] * inv,
                                         out[e + 2] * inv, out[e + 3] * inv);
}

// ---------------- launcher --------------------------------------------------
extern "C" void kernel_launch(void* const* d_in, const int* in_sizes, int n_in,
                              void* d_out, int out_size)
{
    const float* x  = (const float*)d_in[0];
    const float* Wq = (const float*)d_in[1];
    const float* bq = (const float*)d_in[2];
    const float* Wk = (const float*)d_in[3];
    const float* bk = (const float*)d_in[4];
    const float* Wv = (const float*)d_in[5];
    const float* bv = (const float*)d_in[6];
    const float* Wo = (const float*)d_in[7];
    const float* bo = (const float*)d_in[8];

    const int M   = in_sizes[0] / DIMD;   // B*N = 16384
    const int B   = 4;
    const int seq = M / B;                // 4096

    float *Qp, *Kp, *Vp, *Ap, *KVp, *Zp;
    cudaGetSymbolAddress((void**)&Qp,  g_Q);
    cudaGetSymbolAddress((void**)&Kp,  g_K);
    cudaGetSymbolAddress((void**)&Vp,  g_V);
    cudaGetSymbolAddress((void**)&Ap,  g_A);
    cudaGetSymbolAddress((void**)&KVp, g_KV);
    cudaGetSymbolAddress((void**)&Zp,  g_Z);

    dim3 gblk(DIMD / BN, M / BM);   // (8, 128)

    // projections (phi fused into Q,K) — tf32 tensor cores
    gemm_tf32<1><<<gblk, 256>>>(x, Wq, bq, Qp, M, DIMD);
    gemm_tf32<1><<<gblk, 256>>>(x, Wk, bk, Kp, M, DIMD);
    gemm_tf32<0><<<gblk, 256>>>(x, Wv, bv, Vp, M, DIMD);

    // zero KV / Z accumulators
    zero_kv_kernel<<<(64 * 64 * 64 + 255) / 256, 256>>>(KVp, Zp);

    // KV state + Z (split-K over sequence, atomic combine)
    kv_kernel<<<B * NH * KV_SPLIT, 256>>>(Kp, Vp, KVp, Zp, seq);

    // attention apply + normalization
    attn_kernel<<<dim3(B * NH, seq / 64), 256>>>(Qp, KVp, Zp, Ap, seq);

    // output projection -> d_out
    gemm_tf32<0><<<gblk, 256>>>(Ap, Wo, bo, (float*)d_out, M, DIMD);
}

// round 6
// speedup vs baseline: 4.0507x; 1.5341x over previous
#include <cuda_runtime.h>
#include <cuda_fp16.h>
#include <math.h>
#include <stdint.h>

#define DIMD 1024
#define NH   16
#define HD   64

// ---------------- scratch (device globals: no allocation allowed) ----------
__device__ __half g_Xh[16384 * 1024];          // x in fp16
__device__ __half g_Wh[4 * 1024 * 1024];       // Wq|Wk|Wv|Wo in fp16
__device__ float  g_Q [16384 * 1024];
__device__ float  g_K [16384 * 1024];
__device__ float  g_V [16384 * 1024];
__device__ __half g_Ah[16384 * 1024];          // attn output in fp16
__device__ float  g_KV[64 * 64 * 64];          // [B*H][d][e]
__device__ float  g_Z [64 * 64];               // [B*H][d]

// ---------------- convert inputs to fp16 ------------------------------------
// pairs: x = 8388608, each W = 524288
__global__ void cvt_kernel(const float* __restrict__ x,
                           const float* __restrict__ wq, const float* __restrict__ wk,
                           const float* __restrict__ wv, const float* __restrict__ wo,
                           __half* __restrict__ xh, __half* __restrict__ wh)
{
    int i = blockIdx.x * blockDim.x + threadIdx.x;
    const int XP = 8388608, WP = 524288;
    if (i < XP) {
        float2 v = ((const float2*)x)[i];
        ((__half2*)xh)[i] = __floats2half2_rn(v.x, v.y);
    } else {
        int j = i - XP;
        int sel = j / WP, off = j - sel * WP;
        const float* src = (sel == 0) ? wq : (sel == 1) ? wk : (sel == 2) ? wv : wo;
        float2 v = ((const float2*)src)[off];
        ((__half2*)(wh))[sel * WP + off] = __floats2half2_rn(v.x, v.y);
    }
}

// ---------------- zero kernel (KV + Z in one launch) ------------------------
__global__ void zero_kv_kernel(float* __restrict__ kv, float* __restrict__ z) {
    int i = blockIdx.x * blockDim.x + threadIdx.x;
    if (i < 64 * 64 * 64) kv[i] = 0.0f;
    if (i < 64 * 64)      z[i]  = 0.0f;
}

// ---------------- asm helpers ------------------------------------------------
__device__ __forceinline__ uint32_t smem_u32(const void* p) {
    uint32_t a;
    asm("{ .reg .u64 t; cvta.to.shared.u64 t, %1; cvt.u32.u64 %0, t; }"
        : "=r"(a) : "l"(p));
    return a;
}

#define CP_ASYNC16(dst, src) \
    asm volatile("cp.async.cg.shared.global [%0], [%1], 16;" :: "r"(dst), "l"(src))
#define CP_COMMIT() asm volatile("cp.async.commit_group;" ::: "memory")
#define CP_WAIT(n)  asm volatile("cp.async.wait_group %0;" :: "n"(n) : "memory")

#define LDSM_X4(r0, r1, r2, r3, addr) \
    asm volatile("ldmatrix.sync.aligned.m8n8.x4.shared.b16 {%0,%1,%2,%3}, [%4];" \
                 : "=r"(r0), "=r"(r1), "=r"(r2), "=r"(r3) : "r"(addr))

__device__ __forceinline__ void mma_f16(float* d, const uint32_t* a,
                                        uint32_t b0, uint32_t b1) {
    asm volatile(
        "mma.sync.aligned.m16n8k16.row.col.f32.f16.f16.f32 "
        "{%0,%1,%2,%3}, {%4,%5,%6,%7}, {%8,%9}, {%0,%1,%2,%3};"
        : "+f"(d[0]), "+f"(d[1]), "+f"(d[2]), "+f"(d[3])
        : "r"(a[0]), "r"(a[1]), "r"(a[2]), "r"(a[3]), "r"(b0), "r"(b1));
}

// ---------------- fp16 GEMM: C[m,n] = sum_k A[m,k]*W[n,k] + bias[n] ---------
// A:[M,K] half row-major, W:[1024,K] half row-major, C:[M,1024] float
// ACT=1: phi(x)=elu(x)+1
constexpr int BM = 128, BN = 128, BK = 32;
constexpr int ROWB   = 80;                       // 40 halves = 32 + 8 pad
constexpr int A_STG  = BM * ROWB;                // 10240 B
constexpr int STAGE  = 2 * A_STG;                // 20480 B (A + B)
constexpr int NSTAGE = 4;
constexpr int SMEM_GEMM = NSTAGE * STAGE;        // 81920 B

template <int ACT>
__global__ __launch_bounds__(256, 2)
void gemm_f16(const __half* __restrict__ A, const __half* __restrict__ W,
              const float* __restrict__ bias, float* __restrict__ C,
              int M, int K)
{
    extern __shared__ char smem[];
    const uint32_t sbase = smem_u32(smem);
    const int tid  = threadIdx.x;
    const int lane = tid & 31;
    const int warp = tid >> 5;
    const int wm   = warp & 1;     // 0..1 : 64-row slab
    const int wn   = warp >> 1;    // 0..3 : 32-col slab
    const int bm   = blockIdx.y * BM;
    const int bn   = blockIdx.x * BN;
    const int g    = lane >> 2, t4 = lane & 3;

    // cp.async staging map: 512 16B-chunks per operand, 2 per thread each
    int crow[2], ckc[2];
#pragma unroll
    for (int l = 0; l < 2; l++) {
        int c = tid + 256 * l;
        crow[l] = c >> 2;          // 0..127
        ckc[l]  = c & 3;           // 16B chunk within row (8 halves each)
    }
    const __half* Arow0 = A + (size_t)bm * K;
    const __half* Wrow0 = W + (size_t)bn * K;

    // ldmatrix per-lane offsets
    const int a_r = (lane & 7) + ((lane >> 3) & 1) * 8;
    const int a_k = ((lane >> 4) & 1) * 8;
    const uint32_t a_off = (uint32_t)((wm * 64 + a_r) * ROWB + a_k * 2);
    const int b_r = (lane & 7) + ((lane >> 4) & 1) * 8;
    const int b_k = ((lane >> 3) & 1) * 8;
    const uint32_t b_off = (uint32_t)((wn * 32 + b_r) * ROWB + b_k * 2);

    float acc[4][4][4];
#pragma unroll
    for (int mt = 0; mt < 4; mt++)
#pragma unroll
        for (int nt = 0; nt < 4; nt++)
#pragma unroll
            for (int r = 0; r < 4; r++) acc[mt][nt][r] = 0.0f;

    const int NT = K / BK;   // 32

    // prologue: issue stages 0..2
#pragma unroll
    for (int t = 0; t < 3; t++) {
        uint32_t sa = sbase + t * STAGE;
#pragma unroll
        for (int l = 0; l < 2; l++) {
            uint32_t d = sa + crow[l] * ROWB + ckc[l] * 16;
            CP_ASYNC16(d, Arow0 + (size_t)crow[l] * K + t * BK + ckc[l] * 8);
            CP_ASYNC16(d + A_STG, Wrow0 + (size_t)crow[l] * K + t * BK + ckc[l] * 8);
        }
        CP_COMMIT();
    }

    for (int t = 0; t < NT; t++) {
        CP_WAIT(2);
        __syncthreads();

        // issue stage t+3 (overwrites stage (t+3)&3, safe after the sync)
        if (t + 3 < NT) {
            uint32_t sa = sbase + ((t + 3) & 3) * STAGE;
            int k0 = (t + 3) * BK;
#pragma unroll
            for (int l = 0; l < 2; l++) {
                uint32_t d = sa + crow[l] * ROWB + ckc[l] * 16;
                CP_ASYNC16(d, Arow0 + (size_t)crow[l] * K + k0 + ckc[l] * 8);
                CP_ASYNC16(d + A_STG, Wrow0 + (size_t)crow[l] * K + k0 + ckc[l] * 8);
            }
        }
        CP_COMMIT();

        // compute stage t&3
        const uint32_t sa = sbase + (t & 3) * STAGE;
        const uint32_t sb = sa + A_STG;
#pragma unroll
        for (int ks = 0; ks < 2; ks++) {
            uint32_t ar[4][4], br[2][4];
#pragma unroll
            for (int mt = 0; mt < 4; mt++)
                LDSM_X4(ar[mt][0], ar[mt][1], ar[mt][2], ar[mt][3],
                        sa + a_off + mt * (16 * ROWB) + ks * 32);
#pragma unroll
            for (int q = 0; q < 2; q++)
                LDSM_X4(br[q][0], br[q][1], br[q][2], br[q][3],
                        sb + b_off + q * (16 * ROWB) + ks * 32);
#pragma unroll
            for (int mt = 0; mt < 4; mt++)
#pragma unroll
                for (int nt = 0; nt < 4; nt++)
                    mma_f16(acc[mt][nt], ar[mt],
                            br[nt >> 1][(nt & 1) * 2],
                            br[nt >> 1][(nt & 1) * 2 + 1]);
        }
    }

    // epilogue
#pragma unroll
    for (int mt = 0; mt < 4; mt++) {
#pragma unroll
        for (int nt = 0; nt < 4; nt++) {
            int row = bm + wm * 64 + mt * 16 + g;
            int col = bn + wn * 32 + nt * 8 + t4 * 2;
            float b0 = bias[col], b1 = bias[col + 1];
            float v0 = acc[mt][nt][0] + b0;
            float v1 = acc[mt][nt][1] + b1;
            float v2 = acc[mt][nt][2] + b0;
            float v3 = acc[mt][nt][3] + b1;
            if (ACT) {
                v0 = (v0 > 0.0f) ? (v0 + 1.0f) : expf(v0);
                v1 = (v1 > 0.0f) ? (v1 + 1.0f) : expf(v1);
                v2 = (v2 > 0.0f) ? (v2 + 1.0f) : expf(v2);
                v3 = (v3 > 0.0f) ? (v3 + 1.0f) : expf(v3);
            }
            *(float2*)&C[(size_t)row * DIMD + col]       = make_float2(v0, v1);
            *(float2*)&C[(size_t)(row + 8) * DIMD + col] = make_float2(v2, v3);
        }
    }
}

// ---------------- KV state: KV[bh][d][e] = sum_n K[n,d]*V[n,e]; Z = sum K --
#define KV_SPLIT 8

__global__ __launch_bounds__(256)
void kv_kernel(const float* __restrict__ Kmat, const float* __restrict__ Vmat,
               float* __restrict__ KV, float* __restrict__ Z, int seq)
{
    const int bh    = blockIdx.x / KV_SPLIT;
    const int chunk = blockIdx.x % KV_SPLIT;
    const int b = bh / NH, h = bh % NH;
    const int rowsPer = seq / KV_SPLIT;
    const int n0 = chunk * rowsPer;

    const int tid = threadIdx.x;
    const int ti = tid >> 4;
    const int tj = tid & 15;

    __shared__ float Ks[8][64];
    __shared__ float Vs[8][64];

    float acc[4][4];
#pragma unroll
    for (int i = 0; i < 4; i++)
#pragma unroll
        for (int j = 0; j < 4; j++) acc[i][j] = 0.0f;
    float z = 0.0f;

    const size_t base = ((size_t)b * seq) * DIMD + h * HD;

    for (int n = n0; n < n0 + rowsPer; n += 8) {
#pragma unroll
        for (int li = 0; li < 2; li++) {
            int idx = tid + li * 256;
            int r = idx >> 6, c = idx & 63;
            size_t gaddr = base + (size_t)(n + r) * DIMD + c;
            Ks[r][c] = Kmat[gaddr];
            Vs[r][c] = Vmat[gaddr];
        }
        __syncthreads();
#pragma unroll
        for (int r = 0; r < 8; r++) {
            float kd[4], ve[4];
#pragma unroll
            for (int i = 0; i < 4; i++) kd[i] = Ks[r][ti * 4 + i];
#pragma unroll
            for (int j = 0; j < 4; j++) ve[j] = Vs[r][tj * 4 + j];
#pragma unroll
            for (int i = 0; i < 4; i++)
#pragma unroll
                for (int j = 0; j < 4; j++)
                    acc[i][j] += kd[i] * ve[j];
            if (tid < 64) z += Ks[r][tid];
        }
        __syncthreads();
    }

    float* kvp = KV + (size_t)bh * HD * HD;
#pragma unroll
    for (int i = 0; i < 4; i++)
#pragma unroll
        for (int j = 0; j < 4; j++)
            atomicAdd(&kvp[(ti * 4 + i) * HD + tj * 4 + j], acc[i][j]);
    if (tid < 64) atomicAdd(&Z[bh * HD + tid], z);
}

// ---------------- apply: out[n,e] = (Q[n,:]·KV[:,e]) / (Q[n,:]·Z + eps) ----
// writes fp16 (input to the final GEMM)
__global__ __launch_bounds__(256)
void attn_kernel(const float* __restrict__ Qmat, const float* __restrict__ KV,
                 const float* __restrict__ Z, __half* __restrict__ Out, int seq)
{
    const int bh = blockIdx.x;
    const int b = bh / NH, h = bh % NH;
    const int n0 = blockIdx.y * 64;
    const int tid = threadIdx.x;

    __shared__ float KVs[64][64];
    __shared__ float Qs[64][64];
    __shared__ float Zs[64];

    const float* kvp = KV + (size_t)bh * HD * HD;
    for (int i = tid; i < 4096; i += 256) KVs[i >> 6][i & 63] = kvp[i];
    if (tid < 64) Zs[tid] = Z[bh * HD + tid];

    const size_t base = ((size_t)b * seq) * DIMD + h * HD;
    for (int i = tid; i < 4096; i += 256) {
        int r = i >> 6, c = i & 63;
        Qs[r][c] = Qmat[base + (size_t)(n0 + r) * DIMD + c];
    }
    __syncthreads();

    const int r = tid >> 2;
    const int g = tid & 3;

    float out[16];
#pragma unroll
    for (int e = 0; e < 16; e++) out[e] = 0.0f;
    float nrm = 0.0f;

#pragma unroll
    for (int d = 0; d < 64; d++) {
        float q = Qs[r][d];
        nrm += q * Zs[d];
#pragma unroll
        for (int e = 0; e < 16; e++)
            out[e] += q * KVs[d][g * 16 + e];
    }

    float inv = 1.0f / (nrm + 1e-6f);
    __half* op = Out + base + (size_t)(n0 + r) * DIMD + g * 16;
#pragma unroll
    for (int e = 0; e < 16; e += 2)
        *(__half2*)(op + e) = __floats2half2_rn(out[e] * inv, out[e + 1] * inv);
}

// ---------------- launcher --------------------------------------------------
extern "C" void kernel_launch(void* const* d_in, const int* in_sizes, int n_in,
                              void* d_out, int out_size)
{
    const float* x  = (const float*)d_in[0];
    const float* Wq = (const float*)d_in[1];
    const float* bq = (const float*)d_in[2];
    const float* Wk = (const float*)d_in[3];
    const float* bk = (const float*)d_in[4];
    const float* Wv = (const float*)d_in[5];
    const float* bv = (const float*)d_in[6];
    const float* Wo = (const float*)d_in[7];
    const float* bo = (const float*)d_in[8];

    const int M   = in_sizes[0] / DIMD;   // 16384
    const int B   = 4;
    const int seq = M / B;                // 4096

    __half *Xh, *Wh, *Ah;
    float *Qp, *Kp, *Vp, *KVp, *Zp;
    cudaGetSymbolAddress((void**)&Xh,  g_Xh);
    cudaGetSymbolAddress((void**)&Wh,  g_Wh);
    cudaGetSymbolAddress((void**)&Qp,  g_Q);
    cudaGetSymbolAddress((void**)&Kp,  g_K);
    cudaGetSymbolAddress((void**)&Vp,  g_V);
    cudaGetSymbolAddress((void**)&Ah,  g_Ah);
    cudaGetSymbolAddress((void**)&KVp, g_KV);
    cudaGetSymbolAddress((void**)&Zp,  g_Z);

    cudaFuncSetAttribute(gemm_f16<0>, cudaFuncAttributeMaxDynamicSharedMemorySize, SMEM_GEMM);
    cudaFuncSetAttribute(gemm_f16<1>, cudaFuncAttributeMaxDynamicSharedMemorySize, SMEM_GEMM);

    // 0: convert inputs to fp16 (10485760 pairs)
    cvt_kernel<<<10485760 / 256, 256>>>(x, Wq, Wk, Wv, Wo, Xh, Wh);

    dim3 gblk(DIMD / BN, M / BM);   // (8, 128)

    // 1-3: projections (phi fused into Q,K); slot 3 (gemm V) gets profiled
    gemm_f16<1><<<gblk, 256, SMEM_GEMM>>>(Xh, Wh + 0 * 1048576, bq, Qp, M, DIMD);
    gemm_f16<1><<<gblk, 256, SMEM_GEMM>>>(Xh, Wh + 1 * 1048576, bk, Kp, M, DIMD);
    gemm_f16<0><<<gblk, 256, SMEM_GEMM>>>(Xh, Wh + 2 * 1048576, bv, Vp, M, DIMD);

    // 4: zero KV / Z accumulators
    zero_kv_kernel<<<(64 * 64 * 64 + 255) / 256, 256>>>(KVp, Zp);

    // 5: KV state + Z (split-K over sequence, atomic combine)
    kv_kernel<<<B * NH * KV_SPLIT, 256>>>(Kp, Vp, KVp, Zp, seq);

    // 6: attention apply + normalization (writes fp16)
    attn_kernel<<<dim3(B * NH, seq / 64), 256>>>(Qp, KVp, Zp, Ah, seq);

    // 7: output projection -> d_out
    gemm_f16<0><<<gblk, 256, SMEM_GEMM>>>(Ah, Wh + 3 * 1048576, bo, (float*)d_out, M, DIMD);
}

// round 7
// speedup vs baseline: 4.9827x; 1.2301x over previous
#include <cuda_runtime.h>
#include <cuda_fp16.h>
#include <math.h>
#include <stdint.h>

#define DIMD 1024
#define NH   16
#define HD   64

// ---------------- scratch (device globals: no allocation allowed) ----------
__device__ __half g_Xh[16384 * 1024];          // x in fp16
__device__ __half g_Wh[4 * 1024 * 1024];       // Wq|Wk|Wv|Wo in fp16
__device__ __half g_Qh[16384 * 1024];          // phi(Q) fp16
__device__ __half g_Kh[16384 * 1024];          // phi(K) fp16
__device__ __half g_Vh[16384 * 1024];          // V fp16
__device__ __half g_Ah[16384 * 1024];          // attn output fp16
__device__ float  g_KV[64 * 64 * 64];          // [B*H][d][e] fp32
__device__ float  g_Z [64 * 64];               // [B*H][d]   fp32

// ---------------- convert inputs to fp16 ------------------------------------
__global__ void cvt_kernel(const float* __restrict__ x,
                           const float* __restrict__ wq, const float* __restrict__ wk,
                           const float* __restrict__ wv, const float* __restrict__ wo,
                           __half* __restrict__ xh, __half* __restrict__ wh)
{
    int i = blockIdx.x * blockDim.x + threadIdx.x;
    const int XP = 8388608, WP = 524288;
    if (i < XP) {
        float2 v = ((const float2*)x)[i];
        ((__half2*)xh)[i] = __floats2half2_rn(v.x, v.y);
    } else {
        int j = i - XP;
        int sel = j / WP, off = j - sel * WP;
        const float* src = (sel == 0) ? wq : (sel == 1) ? wk : (sel == 2) ? wv : wo;
        float2 v = ((const float2*)src)[off];
        ((__half2*)(wh))[sel * WP + off] = __floats2half2_rn(v.x, v.y);
    }
}

// ---------------- zero kernel (KV + Z in one launch) ------------------------
__global__ void zero_kv_kernel(float* __restrict__ kv, float* __restrict__ z) {
    int i = blockIdx.x * blockDim.x + threadIdx.x;
    if (i < 64 * 64 * 64) kv[i] = 0.0f;
    if (i < 64 * 64)      z[i]  = 0.0f;
}

// ---------------- asm helpers ------------------------------------------------
__device__ __forceinline__ uint32_t smem_u32(const void* p) {
    uint32_t a;
    asm("{ .reg .u64 t; cvta.to.shared.u64 t, %1; cvt.u32.u64 %0, t; }"
        : "=r"(a) : "l"(p));
    return a;
}

#define CP_ASYNC16(dst, src) \
    asm volatile("cp.async.cg.shared.global [%0], [%1], 16;" :: "r"(dst), "l"(src))
#define CP_COMMIT() asm volatile("cp.async.commit_group;" ::: "memory")
#define CP_WAIT(n)  asm volatile("cp.async.wait_group %0;" :: "n"(n) : "memory")

#define LDSM_X4(r0, r1, r2, r3, addr) \
    asm volatile("ldmatrix.sync.aligned.m8n8.x4.shared.b16 {%0,%1,%2,%3}, [%4];" \
                 : "=r"(r0), "=r"(r1), "=r"(r2), "=r"(r3) : "r"(addr))

__device__ __forceinline__ void mma_f16(float* d, const uint32_t* a,
                                        uint32_t b0, uint32_t b1) {
    asm volatile(
        "mma.sync.aligned.m16n8k16.row.col.f32.f16.f16.f32 "
        "{%0,%1,%2,%3}, {%4,%5,%6,%7}, {%8,%9}, {%0,%1,%2,%3};"
        : "+f"(d[0]), "+f"(d[1]), "+f"(d[2]), "+f"(d[3])
        : "r"(a[0]), "r"(a[1]), "r"(a[2]), "r"(a[3]), "r"(b0), "r"(b1));
}

// ---------------- fp16 GEMM: C[m,n] = sum_k A[m,k]*W[n,k] + bias[n] ---------
// A:[M,K] half row-major, W:[1024,K] half row-major
// OUTH=1: C is __half; else float.  ACT=1: phi(x)=elu(x)+1
constexpr int BM = 128, BN = 128, BK = 32;
constexpr int ROWB   = 80;                       // 40 halves = 32 + 8 pad
constexpr int A_STG  = BM * ROWB;                // 10240 B
constexpr int STAGE  = 2 * A_STG;                // 20480 B
constexpr int NSTAGE = 4;
constexpr int SMEM_GEMM = NSTAGE * STAGE;        // 81920 B

template <int ACT, int OUTH>
__global__ __launch_bounds__(256, 2)
void gemm_f16(const __half* __restrict__ A, const __half* __restrict__ W,
              const float* __restrict__ bias, void* __restrict__ Cv,
              int M, int K)
{
    extern __shared__ char smem[];
    const uint32_t sbase = smem_u32(smem);
    const int tid  = threadIdx.x;
    const int lane = tid & 31;
    const int warp = tid >> 5;
    const int wm   = warp & 1;
    const int wn   = warp >> 1;
    const int bm   = blockIdx.y * BM;
    const int bn   = blockIdx.x * BN;
    const int g    = lane >> 2, t4 = lane & 3;

    int crow[2], ckc[2];
#pragma unroll
    for (int l = 0; l < 2; l++) {
        int c = tid + 256 * l;
        crow[l] = c >> 2;
        ckc[l]  = c & 3;
    }
    const __half* Arow0 = A + (size_t)bm * K;
    const __half* Wrow0 = W + (size_t)bn * K;

    const int a_r = (lane & 7) + ((lane >> 3) & 1) * 8;
    const int a_k = ((lane >> 4) & 1) * 8;
    const uint32_t a_off = (uint32_t)((wm * 64 + a_r) * ROWB + a_k * 2);
    const int b_r = (lane & 7) + ((lane >> 4) & 1) * 8;
    const int b_k = ((lane >> 3) & 1) * 8;
    const uint32_t b_off = (uint32_t)((wn * 32 + b_r) * ROWB + b_k * 2);

    float acc[4][4][4];
#pragma unroll
    for (int mt = 0; mt < 4; mt++)
#pragma unroll
        for (int nt = 0; nt < 4; nt++)
#pragma unroll
            for (int r = 0; r < 4; r++) acc[mt][nt][r] = 0.0f;

    const int NT = K / BK;

#pragma unroll
    for (int t = 0; t < 3; t++) {
        uint32_t sa = sbase + t * STAGE;
#pragma unroll
        for (int l = 0; l < 2; l++) {
            uint32_t d = sa + crow[l] * ROWB + ckc[l] * 16;
            CP_ASYNC16(d, Arow0 + (size_t)crow[l] * K + t * BK + ckc[l] * 8);
            CP_ASYNC16(d + A_STG, Wrow0 + (size_t)crow[l] * K + t * BK + ckc[l] * 8);
        }
        CP_COMMIT();
    }

    for (int t = 0; t < NT; t++) {
        CP_WAIT(2);
        __syncthreads();

        if (t + 3 < NT) {
            uint32_t sa = sbase + ((t + 3) & 3) * STAGE;
            int k0 = (t + 3) * BK;
#pragma unroll
            for (int l = 0; l < 2; l++) {
                uint32_t d = sa + crow[l] * ROWB + ckc[l] * 16;
                CP_ASYNC16(d, Arow0 + (size_t)crow[l] * K + k0 + ckc[l] * 8);
                CP_ASYNC16(d + A_STG, Wrow0 + (size_t)crow[l] * K + k0 + ckc[l] * 8);
            }
        }
        CP_COMMIT();

        const uint32_t sa = sbase + (t & 3) * STAGE;
        const uint32_t sb = sa + A_STG;
#pragma unroll
        for (int ks = 0; ks < 2; ks++) {
            uint32_t ar[4][4], br[2][4];
#pragma unroll
            for (int mt = 0; mt < 4; mt++)
                LDSM_X4(ar[mt][0], ar[mt][1], ar[mt][2], ar[mt][3],
                        sa + a_off + mt * (16 * ROWB) + ks * 32);
#pragma unroll
            for (int q = 0; q < 2; q++)
                LDSM_X4(br[q][0], br[q][1], br[q][2], br[q][3],
                        sb + b_off + q * (16 * ROWB) + ks * 32);
#pragma unroll
            for (int mt = 0; mt < 4; mt++)
#pragma unroll
                for (int nt = 0; nt < 4; nt++)
                    mma_f16(acc[mt][nt], ar[mt],
                            br[nt >> 1][(nt & 1) * 2],
                            br[nt >> 1][(nt & 1) * 2 + 1]);
        }
    }

#pragma unroll
    for (int mt = 0; mt < 4; mt++) {
#pragma unroll
        for (int nt = 0; nt < 4; nt++) {
            int row = bm + wm * 64 + mt * 16 + g;
            int col = bn + wn * 32 + nt * 8 + t4 * 2;
            float b0 = bias[col], b1 = bias[col + 1];
            float v0 = acc[mt][nt][0] + b0;
            float v1 = acc[mt][nt][1] + b1;
            float v2 = acc[mt][nt][2] + b0;
            float v3 = acc[mt][nt][3] + b1;
            if (ACT) {
                v0 = (v0 > 0.0f) ? (v0 + 1.0f) : expf(v0);
                v1 = (v1 > 0.0f) ? (v1 + 1.0f) : expf(v1);
                v2 = (v2 > 0.0f) ? (v2 + 1.0f) : expf(v2);
                v3 = (v3 > 0.0f) ? (v3 + 1.0f) : expf(v3);
            }
            if (OUTH) {
                __half* C = (__half*)Cv;
                *(__half2*)&C[(size_t)row * DIMD + col]       = __floats2half2_rn(v0, v1);
                *(__half2*)&C[(size_t)(row + 8) * DIMD + col] = __floats2half2_rn(v2, v3);
            } else {
                float* C = (float*)Cv;
                *(float2*)&C[(size_t)row * DIMD + col]       = make_float2(v0, v1);
                *(float2*)&C[(size_t)(row + 8) * DIMD + col] = make_float2(v2, v3);
            }
        }
    }
}

// ---------------- KV state: KV[bh][d][e] = sum_n K[n,d]*V[n,e]; Z = sum K --
#define KV_SPLIT 8

__global__ __launch_bounds__(256)
void kv_kernel(const __half* __restrict__ Kmat, const __half* __restrict__ Vmat,
               float* __restrict__ KV, float* __restrict__ Z, int seq)
{
    const int bh    = blockIdx.x / KV_SPLIT;
    const int chunk = blockIdx.x % KV_SPLIT;
    const int b = bh / NH, h = bh % NH;
    const int rowsPer = seq / KV_SPLIT;
    const int n0 = chunk * rowsPer;

    const int tid = threadIdx.x;
    const int ti = tid >> 4;   // d group 0..15
    const int tj = tid & 15;   // e group 0..15

    __shared__ __align__(16) float Ks[8][64];
    __shared__ __align__(16) float Vs[8][64];

    float acc[4][4];
#pragma unroll
    for (int i = 0; i < 4; i++)
#pragma unroll
        for (int j = 0; j < 4; j++) acc[i][j] = 0.0f;
    float z = 0.0f;

    const size_t base = ((size_t)b * seq) * DIMD + h * HD;
    const int sr = tid >> 5, sc2 = tid & 31;   // staging: half2 per thread

    for (int n = n0; n < n0 + rowsPer; n += 8) {
        {
            size_t gaddr = base + (size_t)(n + sr) * DIMD + sc2 * 2;
            float2 kv2 = __half22float2(*(const __half2*)&Kmat[gaddr]);
            float2 vv2 = __half22float2(*(const __half2*)&Vmat[gaddr]);
            *(float2*)&Ks[sr][sc2 * 2] = kv2;
            *(float2*)&Vs[sr][sc2 * 2] = vv2;
        }
        __syncthreads();
#pragma unroll
        for (int r = 0; r < 8; r++) {
            float4 kd = *(const float4*)&Ks[r][ti * 4];
            float4 ve = *(const float4*)&Vs[r][tj * 4];
            float kda[4] = {kd.x, kd.y, kd.z, kd.w};
            float vea[4] = {ve.x, ve.y, ve.z, ve.w};
#pragma unroll
            for (int i = 0; i < 4; i++)
#pragma unroll
                for (int j = 0; j < 4; j++)
                    acc[i][j] += kda[i] * vea[j];
            if (tid < 64) z += Ks[r][tid];
        }
        __syncthreads();
    }

    float* kvp = KV + (size_t)bh * HD * HD;
#pragma unroll
    for (int i = 0; i < 4; i++)
#pragma unroll
        for (int j = 0; j < 4; j++)
            atomicAdd(&kvp[(ti * 4 + i) * HD + tj * 4 + j], acc[i][j]);
    if (tid < 64) atomicAdd(&Z[bh * HD + tid], z);
}

// ---------------- apply: out[n,e] = (Q[n,:]·KV[:,e]) / (Q[n,:]·Z + eps) ----
// 128-row tiles, 2 rows/thread, float4 KV loads; Q fp16 in, out fp16
constexpr int QSTR = 68;   // half stride (64 + 4 pad): conflict-free scalar reads

__global__ __launch_bounds__(256)
void attn_kernel(const __half* __restrict__ Qmat, const float* __restrict__ KV,
                 const float* __restrict__ Z, __half* __restrict__ Out, int seq)
{
    const int bh = blockIdx.x;
    const int b = bh / NH, h = bh % NH;
    const int n0 = blockIdx.y * 128;
    const int tid = threadIdx.x;

    __shared__ __align__(16) float  KVs[64][64];
    __shared__ __align__(16) __half Qs[128][QSTR];
    __shared__ float Zs[64];

    const float* kvp = KV + (size_t)bh * HD * HD;
    for (int i = tid; i < 4096; i += 256) KVs[i >> 6][i & 63] = kvp[i];
    if (tid < 64) Zs[tid] = Z[bh * HD + tid];

    const size_t base = ((size_t)b * seq) * DIMD + h * HD;
    // stage Q: 128 rows x 64 halves = 4096 half2; 16 per thread
#pragma unroll
    for (int l = 0; l < 16; l++) {
        int i = tid + 256 * l;
        int r = i >> 5, c2 = i & 31;
        *(__half2*)&Qs[r][c2 * 2] = *(const __half2*)&Qmat[base + (size_t)(n0 + r) * DIMD + c2 * 2];
    }
    __syncthreads();

    const int r = tid >> 2;    // rows r and r+64
    const int g = tid & 3;     // 16-col group

    float out0[16], out1[16];
#pragma unroll
    for (int e = 0; e < 16; e++) { out0[e] = 0.0f; out1[e] = 0.0f; }
    float nrm0 = 0.0f, nrm1 = 0.0f;

#pragma unroll 16
    for (int d = 0; d < 64; d++) {
        float q0 = __half2float(Qs[r][d]);
        float q1 = __half2float(Qs[r + 64][d]);
        float zz = Zs[d];
        nrm0 += q0 * zz;
        nrm1 += q1 * zz;
#pragma unroll
        for (int c = 0; c < 4; c++) {
            float4 kv4 = *(const float4*)&KVs[d][g * 16 + c * 4];
            out0[c * 4 + 0] += q0 * kv4.x; out1[c * 4 + 0] += q1 * kv4.x;
            out0[c * 4 + 1] += q0 * kv4.y; out1[c * 4 + 1] += q1 * kv4.y;
            out0[c * 4 + 2] += q0 * kv4.z; out1[c * 4 + 2] += q1 * kv4.z;
            out0[c * 4 + 3] += q0 * kv4.w; out1[c * 4 + 3] += q1 * kv4.w;
        }
    }

    float inv0 = 1.0f / (nrm0 + 1e-6f);
    float inv1 = 1.0f / (nrm1 + 1e-6f);
    __half* op0 = Out + base + (size_t)(n0 + r) * DIMD + g * 16;
    __half* op1 = Out + base + (size_t)(n0 + r + 64) * DIMD + g * 16;
#pragma unroll
    for (int e = 0; e < 16; e += 2) {
        *(__half2*)(op0 + e) = __floats2half2_rn(out0[e] * inv0, out0[e + 1] * inv0);
        *(__half2*)(op1 + e) = __floats2half2_rn(out1[e] * inv1, out1[e + 1] * inv1);
    }
}

// ---------------- launcher --------------------------------------------------
extern "C" void kernel_launch(void* const* d_in, const int* in_sizes, int n_in,
                              void* d_out, int out_size)
{
    const float* x  = (const float*)d_in[0];
    const float* Wq = (const float*)d_in[1];
    const float* bq = (const float*)d_in[2];
    const float* Wk = (const float*)d_in[3];
    const float* bk = (const float*)d_in[4];
    const float* Wv = (const float*)d_in[5];
    const float* bv = (const float*)d_in[6];
    const float* Wo = (const float*)d_in[7];
    const float* bo = (const float*)d_in[8];

    const int M   = in_sizes[0] / DIMD;   // 16384
    const int B   = 4;
    const int seq = M / B;                // 4096

    __half *Xh, *Wh, *Qh, *Kh, *Vh, *Ah;
    float *KVp, *Zp;
    cudaGetSymbolAddress((void**)&Xh,  g_Xh);
    cudaGetSymbolAddress((void**)&Wh,  g_Wh);
    cudaGetSymbolAddress((void**)&Qh,  g_Qh);
    cudaGetSymbolAddress((void**)&Kh,  g_Kh);
    cudaGetSymbolAddress((void**)&Vh,  g_Vh);
    cudaGetSymbolAddress((void**)&Ah,  g_Ah);
    cudaGetSymbolAddress((void**)&KVp, g_KV);
    cudaGetSymbolAddress((void**)&Zp,  g_Z);

    cudaFuncSetAttribute(gemm_f16<0, 0>, cudaFuncAttributeMaxDynamicSharedMemorySize, SMEM_GEMM);
    cudaFuncSetAttribute(gemm_f16<0, 1>, cudaFuncAttributeMaxDynamicSharedMemorySize, SMEM_GEMM);
    cudaFuncSetAttribute(gemm_f16<1, 1>, cudaFuncAttributeMaxDynamicSharedMemorySize, SMEM_GEMM);

    // 0: convert inputs to fp16
    cvt_kernel<<<10485760 / 256, 256>>>(x, Wq, Wk, Wv, Wo, Xh, Wh);

    dim3 gblk(DIMD / BN, M / BM);   // (8, 128)

    // 1-3: projections (phi fused into Q,K), fp16 outputs
    gemm_f16<1, 1><<<gblk, 256, SMEM_GEMM>>>(Xh, Wh + 0 * 1048576, bq, Qh, M, DIMD);
    gemm_f16<1, 1><<<gblk, 256, SMEM_GEMM>>>(Xh, Wh + 1 * 1048576, bk, Kh, M, DIMD);
    gemm_f16<0, 1><<<gblk, 256, SMEM_GEMM>>>(Xh, Wh + 2 * 1048576, bv, Vh, M, DIMD);

    // 4: zero KV / Z accumulators
    zero_kv_kernel<<<(64 * 64 * 64 + 255) / 256, 256>>>(KVp, Zp);

    // 5: KV state + Z
    kv_kernel<<<B * NH * KV_SPLIT, 256>>>(Kh, Vh, KVp, Zp, seq);

    // 6: attention apply + normalization (fp16 out)
    attn_kernel<<<dim3(B * NH, seq / 128), 256>>>(Qh, KVp, Zp, Ah, seq);

    // 7: output projection -> d_out (fp32)
    gemm_f16<0, 0><<<gblk, 256, SMEM_GEMM>>>(Ah, Wh + 3 * 1048576, bo, d_out, M, DIMD);
}

// round 8
// speedup vs baseline: 6.6820x; 1.3410x over previous
#include <cuda_runtime.h>
#include <cuda_fp16.h>
#include <math.h>
#include <stdint.h>

#define DIMD 1024
#define NH   16
#define HD   64

// ---------------- scratch (device globals: no allocation allowed) ----------
__device__ __half g_Xh[16384 * 1024];          // x fp16
__device__ __half g_Wh[4 * 1024 * 1024];       // Wq|Wk|Wv|Wo fp16
__device__ __half g_Qh[16384 * 1024];          // phi(Q) fp16
__device__ __half g_Kh[16384 * 1024];          // phi(K) fp16
__device__ __half g_Vh[16384 * 1024];          // V fp16
__device__ __half g_Ah[16384 * 1024];          // attn out fp16
__device__ float  g_KV[64 * 64 * 64];          // [bh][d][e] fp32
__device__ float  g_Z [64 * 64];               // [bh][d] fp32
__device__ __half g_KVZ[64 * 72 * 64];         // [bh][e-row 0..71][d] fp16

// ---------------- convert inputs to fp16 ------------------------------------
__global__ void cvt_kernel(const float* __restrict__ x,
                           const float* __restrict__ wq, const float* __restrict__ wk,
                           const float* __restrict__ wv, const float* __restrict__ wo,
                           __half* __restrict__ xh, __half* __restrict__ wh)
{
    int i = blockIdx.x * blockDim.x + threadIdx.x;
    const int XP = 8388608, WP = 524288;
    if (i < XP) {
        float2 v = ((const float2*)x)[i];
        ((__half2*)xh)[i] = __floats2half2_rn(v.x, v.y);
    } else {
        int j = i - XP;
        int sel = j / WP, off = j - sel * WP;
        const float* src = (sel == 0) ? wq : (sel == 1) ? wk : (sel == 2) ? wv : wo;
        float2 v = ((const float2*)src)[off];
        ((__half2*)(wh))[sel * WP + off] = __floats2half2_rn(v.x, v.y);
    }
}

// ---------------- zero kernel (KV + Z) --------------------------------------
__global__ void zero_kv_kernel(float* __restrict__ kv, float* __restrict__ z) {
    int i = blockIdx.x * blockDim.x + threadIdx.x;
    if (i < 64 * 64 * 64) kv[i] = 0.0f;
    if (i < 64 * 64)      z[i]  = 0.0f;
}

// ---------------- KVZ build: KVZ[bh][e][d] = KV[bh][d][e]; row64=Z; 65+=0 --
__global__ void kvz_kernel(const float* __restrict__ KV, const float* __restrict__ Z,
                           __half* __restrict__ KVZ)
{
    int i = blockIdx.x * blockDim.x + threadIdx.x;   // 64*72*64
    if (i >= 64 * 72 * 64) return;
    int d  = i & 63;
    int r  = (i >> 6) % 72;
    int bh = i / (72 * 64);
    float v = 0.0f;
    if (r < 64)       v = KV[(bh * 64 + d) * 64 + r];
    else if (r == 64) v = Z[bh * 64 + d];
    KVZ[i] = __float2half(v);
}

// ---------------- asm helpers ------------------------------------------------
__device__ __forceinline__ uint32_t smem_u32(const void* p) {
    uint32_t a;
    asm("{ .reg .u64 t; cvta.to.shared.u64 t, %1; cvt.u32.u64 %0, t; }"
        : "=r"(a) : "l"(p));
    return a;
}

#define CP_ASYNC16(dst, src) \
    asm volatile("cp.async.cg.shared.global [%0], [%1], 16;" :: "r"(dst), "l"(src))
#define CP_COMMIT() asm volatile("cp.async.commit_group;" ::: "memory")
#define CP_WAIT(n)  asm volatile("cp.async.wait_group %0;" :: "n"(n) : "memory")

#define LDSM_X4(r0, r1, r2, r3, addr) \
    asm volatile("ldmatrix.sync.aligned.m8n8.x4.shared.b16 {%0,%1,%2,%3}, [%4];" \
                 : "=r"(r0), "=r"(r1), "=r"(r2), "=r"(r3) : "r"(addr))
#define LDSM_X4T(r0, r1, r2, r3, addr) \
    asm volatile("ldmatrix.sync.aligned.m8n8.x4.trans.shared.b16 {%0,%1,%2,%3}, [%4];" \
                 : "=r"(r0), "=r"(r1), "=r"(r2), "=r"(r3) : "r"(addr))

__device__ __forceinline__ void mma_f16(float* d, const uint32_t* a,
                                        uint32_t b0, uint32_t b1) {
    asm volatile(
        "mma.sync.aligned.m16n8k16.row.col.f32.f16.f16.f32 "
        "{%0,%1,%2,%3}, {%4,%5,%6,%7}, {%8,%9}, {%0,%1,%2,%3};"
        : "+f"(d[0]), "+f"(d[1]), "+f"(d[2]), "+f"(d[3])
        : "r"(a[0]), "r"(a[1]), "r"(a[2]), "r"(a[3]), "r"(b0), "r"(b1));
}

// ---------------- fp16 GEMM (unchanged from R7) ------------------------------
constexpr int BM = 128, BN = 128, BK = 32;
constexpr int ROWB   = 80;
constexpr int A_STG  = BM * ROWB;
constexpr int STAGE  = 2 * A_STG;
constexpr int NSTAGE = 4;
constexpr int SMEM_GEMM = NSTAGE * STAGE;

template <int ACT, int OUTH>
__global__ __launch_bounds__(256, 2)
void gemm_f16(const __half* __restrict__ A, const __half* __restrict__ W,
              const float* __restrict__ bias, void* __restrict__ Cv,
              int M, int K)
{
    extern __shared__ char smem[];
    const uint32_t sbase = smem_u32(smem);
    const int tid  = threadIdx.x;
    const int lane = tid & 31;
    const int warp = tid >> 5;
    const int wm   = warp & 1;
    const int wn   = warp >> 1;
    const int bm   = blockIdx.y * BM;
    const int bn   = blockIdx.x * BN;
    const int g    = lane >> 2, t4 = lane & 3;

    int crow[2], ckc[2];
#pragma unroll
    for (int l = 0; l < 2; l++) {
        int c = tid + 256 * l;
        crow[l] = c >> 2;
        ckc[l]  = c & 3;
    }
    const __half* Arow0 = A + (size_t)bm * K;
    const __half* Wrow0 = W + (size_t)bn * K;

    const int a_r = (lane & 7) + ((lane >> 3) & 1) * 8;
    const int a_k = ((lane >> 4) & 1) * 8;
    const uint32_t a_off = (uint32_t)((wm * 64 + a_r) * ROWB + a_k * 2);
    const int b_r = (lane & 7) + ((lane >> 4) & 1) * 8;
    const int b_k = ((lane >> 3) & 1) * 8;
    const uint32_t b_off = (uint32_t)((wn * 32 + b_r) * ROWB + b_k * 2);

    float acc[4][4][4];
#pragma unroll
    for (int mt = 0; mt < 4; mt++)
#pragma unroll
        for (int nt = 0; nt < 4; nt++)
#pragma unroll
            for (int r = 0; r < 4; r++) acc[mt][nt][r] = 0.0f;

    const int NT = K / BK;

#pragma unroll
    for (int t = 0; t < 3; t++) {
        uint32_t sa = sbase + t * STAGE;
#pragma unroll
        for (int l = 0; l < 2; l++) {
            uint32_t d = sa + crow[l] * ROWB + ckc[l] * 16;
            CP_ASYNC16(d, Arow0 + (size_t)crow[l] * K + t * BK + ckc[l] * 8);
            CP_ASYNC16(d + A_STG, Wrow0 + (size_t)crow[l] * K + t * BK + ckc[l] * 8);
        }
        CP_COMMIT();
    }

    for (int t = 0; t < NT; t++) {
        CP_WAIT(2);
        __syncthreads();

        if (t + 3 < NT) {
            uint32_t sa = sbase + ((t + 3) & 3) * STAGE;
            int k0 = (t + 3) * BK;
#pragma unroll
            for (int l = 0; l < 2; l++) {
                uint32_t d = sa + crow[l] * ROWB + ckc[l] * 16;
                CP_ASYNC16(d, Arow0 + (size_t)crow[l] * K + k0 + ckc[l] * 8);
                CP_ASYNC16(d + A_STG, Wrow0 + (size_t)crow[l] * K + k0 + ckc[l] * 8);
            }
        }
        CP_COMMIT();

        const uint32_t sa = sbase + (t & 3) * STAGE;
        const uint32_t sb = sa + A_STG;
#pragma unroll
        for (int ks = 0; ks < 2; ks++) {
            uint32_t ar[4][4], br[2][4];
#pragma unroll
            for (int mt = 0; mt < 4; mt++)
                LDSM_X4(ar[mt][0], ar[mt][1], ar[mt][2], ar[mt][3],
                        sa + a_off + mt * (16 * ROWB) + ks * 32);
#pragma unroll
            for (int q = 0; q < 2; q++)
                LDSM_X4(br[q][0], br[q][1], br[q][2], br[q][3],
                        sb + b_off + q * (16 * ROWB) + ks * 32);
#pragma unroll
            for (int mt = 0; mt < 4; mt++)
#pragma unroll
                for (int nt = 0; nt < 4; nt++)
                    mma_f16(acc[mt][nt], ar[mt],
                            br[nt >> 1][(nt & 1) * 2],
                            br[nt >> 1][(nt & 1) * 2 + 1]);
        }
    }

#pragma unroll
    for (int mt = 0; mt < 4; mt++) {
#pragma unroll
        for (int nt = 0; nt < 4; nt++) {
            int row = bm + wm * 64 + mt * 16 + g;
            int col = bn + wn * 32 + nt * 8 + t4 * 2;
            float b0 = bias[col], b1 = bias[col + 1];
            float v0 = acc[mt][nt][0] + b0;
            float v1 = acc[mt][nt][1] + b1;
            float v2 = acc[mt][nt][2] + b0;
            float v3 = acc[mt][nt][3] + b1;
            if (ACT) {
                v0 = (v0 > 0.0f) ? (v0 + 1.0f) : expf(v0);
                v1 = (v1 > 0.0f) ? (v1 + 1.0f) : expf(v1);
                v2 = (v2 > 0.0f) ? (v2 + 1.0f) : expf(v2);
                v3 = (v3 > 0.0f) ? (v3 + 1.0f) : expf(v3);
            }
            if (OUTH) {
                __half* C = (__half*)Cv;
                *(__half2*)&C[(size_t)row * DIMD + col]       = __floats2half2_rn(v0, v1);
                *(__half2*)&C[(size_t)(row + 8) * DIMD + col] = __floats2half2_rn(v2, v3);
            } else {
                float* C = (float*)Cv;
                *(float2*)&C[(size_t)row * DIMD + col]       = make_float2(v0, v1);
                *(float2*)&C[(size_t)(row + 8) * DIMD + col] = make_float2(v2, v3);
            }
        }
    }
}

// ---------------- KV state via mma: KV[d][e] = sum_n K[n,d] V[n,e] ----------
// Both operands transposed from [seq][dim] tiles via ldmatrix.trans.
#define KV_SPLIT 8
constexpr int ROWK = 72;   // halves per staged row (64 + 8 pad)

__global__ __launch_bounds__(256)
void kv_mma_kernel(const __half* __restrict__ Kmat, const __half* __restrict__ Vmat,
                   float* __restrict__ KV, float* __restrict__ Z, int seq)
{
    const int bh    = blockIdx.x / KV_SPLIT;
    const int chunk = blockIdx.x % KV_SPLIT;
    const int b = bh / NH, h = bh % NH;
    const int rowsPer = seq / KV_SPLIT;     // 512
    const int n0 = chunk * rowsPer;

    const int tid  = threadIdx.x;
    const int lane = tid & 31;
    const int warp = tid >> 5;
    const int wm   = warp & 3;     // m16 tile (d)
    const int wn   = warp >> 2;    // n32 slab (e)
    const int g    = lane >> 2, t4 = lane & 3;

    __shared__ __align__(16) __half Ks[64][ROWK];
    __shared__ __align__(16) __half Vs[64][ROWK];

    // trans-ldmatrix lane addressing (byte offsets within staged tile)
    // A (from Ks): row = k + bit4*8, col = m + bit3*8
    const int at_r = (lane & 7) + ((lane >> 4) & 1) * 8;
    const int at_c = wm * 16 + ((lane >> 3) & 1) * 8;
    // B (from Vs): row = k + bit3*8, col = e0 + bit4*8
    const int bt_r = (lane & 7) + ((lane >> 3) & 1) * 8;
    const int bt_cb = ((lane >> 4) & 1) * 8;

    const uint32_t ks_base = smem_u32(&Ks[0][0]);
    const uint32_t vs_base = smem_u32(&Vs[0][0]);

    float acc[4][4];
#pragma unroll
    for (int i = 0; i < 4; i++)
#pragma unroll
        for (int j = 0; j < 4; j++) acc[i][j] = 0.0f;

    // Z partial: col = tid&63, rows (tid>>6)*16 .. +15
    const int zc = tid & 63, zr0 = (tid >> 6) * 16;
    float z = 0.0f;

    const size_t base = ((size_t)b * seq) * DIMD + h * HD;
    int srow[2], sck[2];
#pragma unroll
    for (int l = 0; l < 2; l++) {
        int c = tid + 256 * l;
        srow[l] = c >> 3; sck[l] = (c & 7) * 8;
    }

    for (int n = n0; n < n0 + rowsPer; n += 64) {
#pragma unroll
        for (int l = 0; l < 2; l++) {
            size_t gaddr = base + (size_t)(n + srow[l]) * DIMD + sck[l];
            *(uint4*)&Ks[srow[l]][sck[l]] = *(const uint4*)&Kmat[gaddr];
            *(uint4*)&Vs[srow[l]][sck[l]] = *(const uint4*)&Vmat[gaddr];
        }
        __syncthreads();

#pragma unroll
        for (int ks = 0; ks < 4; ks++) {   // k16 steps over 64 seq rows
            uint32_t ar[4], br[2][4];
            LDSM_X4T(ar[0], ar[1], ar[2], ar[3],
                     ks_base + ((ks * 16 + at_r) * ROWK + at_c) * 2);
#pragma unroll
            for (int q = 0; q < 2; q++)
                LDSM_X4T(br[q][0], br[q][1], br[q][2], br[q][3],
                         vs_base + ((ks * 16 + bt_r) * ROWK + wn * 32 + q * 16 + bt_cb) * 2);
#pragma unroll
            for (int nt = 0; nt < 4; nt++)
                mma_f16(acc[nt], ar,
                        br[nt >> 1][(nt & 1) * 2],
                        br[nt >> 1][(nt & 1) * 2 + 1]);
        }

        // Z column sums (fp32)
#pragma unroll
        for (int r = 0; r < 16; r++)
            z += __half2float(Ks[zr0 + r][zc]);
        __syncthreads();
    }

    float* kvp = KV + (size_t)bh * HD * HD;
#pragma unroll
    for (int nt = 0; nt < 4; nt++) {
        int d0 = wm * 16 + g;
        int e0 = wn * 32 + nt * 8 + t4 * 2;
        atomicAdd(&kvp[d0 * HD + e0],           acc[nt][0]);
        atomicAdd(&kvp[d0 * HD + e0 + 1],       acc[nt][1]);
        atomicAdd(&kvp[(d0 + 8) * HD + e0],     acc[nt][2]);
        atomicAdd(&kvp[(d0 + 8) * HD + e0 + 1], acc[nt][3]);
    }
    atomicAdd(&Z[bh * HD + zc], z);
}

// ---------------- attn via mma: out = (Q @ KVZ^T)[:,0:64] / (col64 + eps) ---
constexpr int ROWQ = 72;

__global__ __launch_bounds__(256)
void attn_mma_kernel(const __half* __restrict__ Qmat, const __half* __restrict__ KVZ,
                     __half* __restrict__ Out, int seq)
{
    const int bh = blockIdx.x;
    const int b = bh / NH, h = bh % NH;
    const int n0 = blockIdx.y * 128;
    const int tid  = threadIdx.x;
    const int lane = tid & 31;
    const int warp = tid >> 5;      // m16 tile
    const int g = lane >> 2, t4 = lane & 3;

    __shared__ __align__(16) __half Qs[128][ROWQ];
    __shared__ __align__(16) __half Bs[80][ROWQ];

    // zero pad rows 72-79 of Bs
    for (int i = tid; i < 8 * ROWQ; i += 256)
        Bs[72 + i / ROWQ][i % ROWQ] = __ushort_as_half(0);

    // stage KVZ rows 0-71 (576 16B chunks)
    const __half* kvzp = KVZ + (size_t)bh * 72 * 64;
#pragma unroll
    for (int l = 0; l < 3; l++) {
        int c = tid + 256 * l;
        if (c < 576) {
            int r = c >> 3, ck = (c & 7) * 8;
            *(uint4*)&Bs[r][ck] = *(const uint4*)&kvzp[r * 64 + ck];
        }
    }

    // stage Q: 128 rows x 64 halves (1024 chunks)
    const size_t base = ((size_t)b * seq) * DIMD + h * HD;
#pragma unroll
    for (int l = 0; l < 4; l++) {
        int c = tid + 256 * l;
        int r = c >> 3, ck = (c & 7) * 8;
        *(uint4*)&Qs[r][ck] = *(const uint4*)&Qmat[base + (size_t)(n0 + r) * DIMD + ck];
    }
    __syncthreads();

    const int a_r = (lane & 7) + ((lane >> 3) & 1) * 8;
    const int a_k = ((lane >> 4) & 1) * 8;
    const uint32_t a_off = (uint32_t)(((warp * 16 + a_r) * ROWQ + a_k) * 2);
    const int b_r = (lane & 7) + ((lane >> 4) & 1) * 8;
    const int b_k = ((lane >> 3) & 1) * 8;
    const uint32_t b_off = (uint32_t)((b_r * ROWQ + b_k) * 2);

    const uint32_t qs_base = smem_u32(&Qs[0][0]);
    const uint32_t bs_base = smem_u32(&Bs[0][0]);

    float acc[9][4];
#pragma unroll
    for (int nt = 0; nt < 9; nt++)
#pragma unroll
        for (int r = 0; r < 4; r++) acc[nt][r] = 0.0f;

#pragma unroll
    for (int ks = 0; ks < 4; ks++) {   // k16 over d=64
        uint32_t ar[4], br[5][4];
        LDSM_X4(ar[0], ar[1], ar[2], ar[3], qs_base + a_off + ks * 32);
#pragma unroll
        for (int q = 0; q < 5; q++)
            LDSM_X4(br[q][0], br[q][1], br[q][2], br[q][3],
                    bs_base + b_off + q * (16 * ROWQ * 2) + ks * 32);
#pragma unroll
        for (int nt = 0; nt < 9; nt++)
            mma_f16(acc[nt], ar,
                    br[nt >> 1][(nt & 1) * 2],
                    br[nt >> 1][(nt & 1) * 2 + 1]);
    }

    // norm = col 64 (tile 8, t4==0, regs c0/c2); broadcast across row lanes
    float nrm0 = __shfl_sync(0xffffffffu, acc[8][0], lane & ~3);
    float nrm1 = __shfl_sync(0xffffffffu, acc[8][2], lane & ~3);
    float inv0 = 1.0f / (nrm0 + 1e-6f);
    float inv1 = 1.0f / (nrm1 + 1e-6f);

    int row0 = n0 + warp * 16 + g;
    __half* op0 = Out + base + (size_t)row0 * DIMD;
    __half* op1 = Out + base + (size_t)(row0 + 8) * DIMD;
#pragma unroll
    for (int nt = 0; nt < 8; nt++) {
        int e = nt * 8 + t4 * 2;
        *(__half2*)(op0 + e) = __floats2half2_rn(acc[nt][0] * inv0, acc[nt][1] * inv0);
        *(__half2*)(op1 + e) = __floats2half2_rn(acc[nt][2] * inv1, acc[nt][3] * inv1);
    }
}

// ---------------- launcher --------------------------------------------------
extern "C" void kernel_launch(void* const* d_in, const int* in_sizes, int n_in,
                              void* d_out, int out_size)
{
    const float* x  = (const float*)d_in[0];
    const float* Wq = (const float*)d_in[1];
    const float* bq = (const float*)d_in[2];
    const float* Wk = (const float*)d_in[3];
    const float* bk = (const float*)d_in[4];
    const float* Wv = (const float*)d_in[5];
    const float* bv = (const float*)d_in[6];
    const float* Wo = (const float*)d_in[7];
    const float* bo = (const float*)d_in[8];

    const int M   = in_sizes[0] / DIMD;   // 16384
    const int B   = 4;
    const int seq = M / B;                // 4096

    __half *Xh, *Wh, *Qh, *Kh, *Vh, *Ah, *KVZh;
    float *KVp, *Zp;
    cudaGetSymbolAddress((void**)&Xh,   g_Xh);
    cudaGetSymbolAddress((void**)&Wh,   g_Wh);
    cudaGetSymbolAddress((void**)&Qh,   g_Qh);
    cudaGetSymbolAddress((void**)&Kh,   g_Kh);
    cudaGetSymbolAddress((void**)&Vh,   g_Vh);
    cudaGetSymbolAddress((void**)&Ah,   g_Ah);
    cudaGetSymbolAddress((void**)&KVZh, g_KVZ);
    cudaGetSymbolAddress((void**)&KVp,  g_KV);
    cudaGetSymbolAddress((void**)&Zp,   g_Z);

    cudaFuncSetAttribute(gemm_f16<0, 0>, cudaFuncAttributeMaxDynamicSharedMemorySize, SMEM_GEMM);
    cudaFuncSetAttribute(gemm_f16<0, 1>, cudaFuncAttributeMaxDynamicSharedMemorySize, SMEM_GEMM);
    cudaFuncSetAttribute(gemm_f16<1, 1>, cudaFuncAttributeMaxDynamicSharedMemorySize, SMEM_GEMM);

    // 0: convert inputs to fp16
    cvt_kernel<<<10485760 / 256, 256>>>(x, Wq, Wk, Wv, Wo, Xh, Wh);

    dim3 gblk(DIMD / BN, M / BM);   // (8, 128)

    // 1-3: projections (phi fused into Q,K), fp16 outputs
    gemm_f16<1, 1><<<gblk, 256, SMEM_GEMM>>>(Xh, Wh + 0 * 1048576, bq, Qh, M, DIMD);
    gemm_f16<1, 1><<<gblk, 256, SMEM_GEMM>>>(Xh, Wh + 1 * 1048576, bk, Kh, M, DIMD);
    gemm_f16<0, 1><<<gblk, 256, SMEM_GEMM>>>(Xh, Wh + 2 * 1048576, bv, Vh, M, DIMD);

    // 4: zero KV / Z
    zero_kv_kernel<<<(64 * 64 * 64 + 255) / 256, 256>>>(KVp, Zp);

    // 5: KV state + Z via tensor cores (split-K, atomic combine)
    kv_mma_kernel<<<B * NH * KV_SPLIT, 256>>>(Kh, Vh, KVp, Zp, seq);

    // 6: build KVZ^T fp16 (Z appended as row 64)
    kvz_kernel<<<(64 * 72 * 64 + 255) / 256, 256>>>(KVp, Zp, KVZh);

    // 7: attention apply + normalization via tensor cores
    attn_mma_kernel<<<dim3(B * NH, seq / 128), 256>>>(Qh, KVZh, Ah, seq);

    // 8: output projection -> d_out (fp32)
    gemm_f16<0, 0><<<gblk, 256, SMEM_GEMM>>>(Ah, Wh + 3 * 1048576, bo, d_out, M, DIMD);
}